// round 12
// baseline (speedup 1.0000x reference)
#include <cuda_runtime.h>
#include <cuda_fp16.h>

#define HDIM 256
#define MAX_E 200000
#define MAX_N 50000
#define MAX_BT (MAX_E * 8)

// ---------------- static scratch ----------------
__device__ float    g_msg_input[MAX_E * HDIM];
__device__ unsigned g_msgA[MAX_E * HDIM / 2];   // fp16 half2-packed
__device__ unsigned g_msgB[MAX_E * HDIM / 2];   // fp16 half2-packed
__device__ float    g_node_alpha[MAX_N * HDIM];
__device__ unsigned g_ns[MAX_N * HDIM / 2];     // fp16 half2-packed
__device__ float    g_m[MAX_N * HDIM];
__device__ float    g_h[MAX_N * HDIM];
__device__ unsigned g_Wht[HDIM * HDIM / 2];     // W_h^T fp16: [n][k] half2-packed
__device__ int      g_cnt[MAX_E];
__device__ int      g_node_ptr[MAX_N + 1];
__device__ int      g_in_idx[MAX_E];
__device__ int      g_bt_ptr[MAX_E + 1];
__device__ int      g_bt_idx[MAX_BT];

// ---------------- helpers ----------------
__device__ __forceinline__ unsigned f2tf(float x) {
    unsigned u; asm("cvt.rna.tf32.f32 %0, %1;" : "=r"(u) : "f"(x)); return u;
}
__device__ __forceinline__ float2 h2f(unsigned u) {
    __half2 h = *reinterpret_cast<__half2*>(&u);
    return __half22float2(h);
}
__device__ __forceinline__ unsigned f2h(float2 v) {
    __half2 h = __float22half2_rn(v);
    return *reinterpret_cast<unsigned*>(&h);
}
__device__ __forceinline__ float4 ldh4(const unsigned* p, long idx) {  // idx multiple of 4 (halves)
    uint2 u = *(const uint2*)&p[idx >> 1];
    float2 a = h2f(u.x), b = h2f(u.y);
    return make_float4(a.x, a.y, b.x, b.y);
}
__device__ __forceinline__ void mma_tf32(float* c, const unsigned* a, const unsigned* b) {
    asm volatile(
        "mma.sync.aligned.m16n8k8.row.col.f32.tf32.tf32.f32 "
        "{%0,%1,%2,%3}, {%4,%5,%6,%7}, {%8,%9}, {%0,%1,%2,%3};\n"
        : "+f"(c[0]), "+f"(c[1]), "+f"(c[2]), "+f"(c[3])
        : "r"(a[0]), "r"(a[1]), "r"(a[2]), "r"(a[3]), "r"(b[0]), "r"(b[1]));
}
__device__ __forceinline__ void mma_f16(float* c, const unsigned* a, const unsigned* b) {
    asm volatile(
        "mma.sync.aligned.m16n8k16.row.col.f32.f16.f16.f32 "
        "{%0,%1,%2,%3}, {%4,%5,%6,%7}, {%8,%9}, {%0,%1,%2,%3};\n"
        : "+f"(c[0]), "+f"(c[1]), "+f"(c[2]), "+f"(c[3])
        : "r"(a[0]), "r"(a[1]), "r"(a[2]), "r"(a[3]), "r"(b[0]), "r"(b[1]));
}

// ---------------- CSR builds ----------------
__global__ void k_zero_cnt(int n) {
    int i = blockIdx.x * blockDim.x + threadIdx.x;
    if (i < n) g_cnt[i] = 0;
}
__global__ void k_count(const int* __restrict__ edst, int E) {
    int e = blockIdx.x * blockDim.x + threadIdx.x;
    if (e < E) atomicAdd(&g_cnt[edst[e]], 1);
}
__global__ void k_scan(int* __restrict__ ptr, int n, int rezero) {
    __shared__ int sh[1024];
    __shared__ int carry;
    int tid = threadIdx.x;
    if (tid == 0) { carry = 0; ptr[0] = 0; }
    __syncthreads();
    for (int base = 0; base < n; base += 1024) {
        int i = base + tid;
        int v = (i < n) ? g_cnt[i] : 0;
        sh[tid] = v; __syncthreads();
        for (int off = 1; off < 1024; off <<= 1) {
            int add = (tid >= off) ? sh[tid - off] : 0;
            __syncthreads();
            sh[tid] += add; __syncthreads();
        }
        if (i < n) { ptr[i + 1] = carry + sh[tid]; if (rezero) g_cnt[i] = 0; }
        __syncthreads();
        if (tid == 0) carry += sh[1023];
        __syncthreads();
    }
}
__global__ void k_place(const int* __restrict__ edst, int E) {
    int e = blockIdx.x * blockDim.x + threadIdx.x;
    if (e >= E) return;
    int v = edst[e];
    int pos = atomicAdd(&g_cnt[v], 1);
    g_in_idx[g_node_ptr[v] + pos] = e;
}
__global__ void k_bt_count(const int* __restrict__ esrc, const int* __restrict__ edst, int E) {
    int e = blockIdx.x * blockDim.x + threadIdx.x;
    if (e >= E) return;
    int sv = esrc[e], dv = edst[e];
    int cnt = 0;
    for (int j = g_node_ptr[sv]; j < g_node_ptr[sv + 1]; j++)
        if (esrc[g_in_idx[j]] == dv) cnt++;
    g_cnt[e] = cnt;
}
__global__ void k_bt_fill(const int* __restrict__ esrc, const int* __restrict__ edst, int E) {
    int e = blockIdx.x * blockDim.x + threadIdx.x;
    if (e >= E) return;
    int sv = esrc[e], dv = edst[e];
    int k = g_bt_ptr[e];
    for (int j = g_node_ptr[sv]; j < g_node_ptr[sv + 1]; j++) {
        int e2 = g_in_idx[j];
        if (esrc[e2] == dv && k < MAX_BT) g_bt_idx[k++] = e2;
    }
}

// ---------------- misc ----------------
__global__ void k_zero_alpha(int n) {
    int i = blockIdx.x * blockDim.x + threadIdx.x;
    if (i < n) g_node_alpha[i] = 0.f;
}
__global__ void k_scatter_alpha(const float* __restrict__ tree_m,
                                const int* __restrict__ tgt,
                                const int* __restrict__ teid, int K) {
    int i = blockIdx.x * blockDim.x + threadIdx.x;
    int k = i >> 8, h = i & 255;
    if (k >= K) return;
    atomicAdd(&g_node_alpha[tgt[k] * HDIM + h], tree_m[teid[k] * HDIM + h]);
}
// W_h^T fp16: g_Wht[n*128 + kw] = {W_h[2kw][n], W_h[2kw+1][n]}
__global__ void k_convWt(const float* __restrict__ W_h) {
    int i = blockIdx.x * blockDim.x + threadIdx.x;
    if (i >= HDIM * HDIM / 2) return;
    int n = i >> 7, kw = i & 127;
    float2 v = make_float2(W_h[(2 * kw) * HDIM + n], W_h[(2 * kw + 1) * HDIM + n]);
    g_Wht[i] = f2h(v);
}

// ---------------- per-node sum: out[v] = alpha[v] + sum msg_in[in(v)] ----------------
__global__ __launch_bounds__(256)
void k_nodesum(int buf, int to_m, int N) {
    const unsigned* __restrict__ msg_in = buf ? g_msgB : g_msgA;
    int v = blockIdx.x * 4 + (threadIdx.x >> 6);
    if (v >= N) return;
    int t4 = (threadIdx.x & 63) * 4;
    float4 acc = *(const float4*)&g_node_alpha[(long)v * HDIM + t4];
    int s = g_node_ptr[v], en = g_node_ptr[v + 1];
    int i = s;
    for (; i + 4 <= en; i += 4) {
        int i0 = g_in_idx[i], i1 = g_in_idx[i + 1], i2 = g_in_idx[i + 2], i3 = g_in_idx[i + 3];
        float4 v0 = ldh4(msg_in, (long)i0 * HDIM + t4);
        float4 v1 = ldh4(msg_in, (long)i1 * HDIM + t4);
        float4 v2 = ldh4(msg_in, (long)i2 * HDIM + t4);
        float4 v3 = ldh4(msg_in, (long)i3 * HDIM + t4);
        acc.x += v0.x + v1.x + v2.x + v3.x;
        acc.y += v0.y + v1.y + v2.y + v3.y;
        acc.z += v0.z + v1.z + v2.z + v3.z;
        acc.w += v0.w + v1.w + v2.w + v3.w;
    }
    for (; i < en; i++) {
        float4 vv = ldh4(msg_in, (long)g_in_idx[i] * HDIM + t4);
        acc.x += vv.x; acc.y += vv.y; acc.z += vv.z; acc.w += vv.w;
    }
    if (to_m) {
        *(float4*)&g_m[(long)v * HDIM + t4] = acc;
    } else {
        uint2 st;
        st.x = f2h(make_float2(acc.x, acc.y));
        st.y = f2h(make_float2(acc.z, acc.w));
        *(uint2*)&g_ns[((long)v * HDIM + t4) >> 1] = st;
    }
}

// ---------------- fused BP: fp16 m16n8k16 MMA, BM=64 x BN=256, 256 threads ----------------
// As: 64 rows x 132 words (128 half2 data + 4 pad)   = 33.8 KB
// Bs: 256 n-rows x 12 words (8 half2 k data + 4 pad) = 12.3 KB
#define ASW 132
#define BSW 12
#define BP_SMEM ((64 * ASW + 256 * BSW) * 4)

__global__ __launch_bounds__(256, 2)
void k_bp_fused(const int* __restrict__ esrc, int E, int buf) {
    const unsigned* __restrict__ msg_in  = buf ? g_msgB : g_msgA;
    unsigned*       __restrict__ msg_out = buf ? g_msgA : g_msgB;

    extern __shared__ unsigned smem_u[];
    unsigned* As = smem_u;             // [64][ASW] half2 words
    unsigned* Bs = smem_u + 64 * ASW;  // [256][BSW] half2 words (W^T tile)

    int tid = threadIdx.x;
    int lane = tid & 31, wid = tid >> 5;
    int gg = lane >> 2, tig = lane & 3;
    int wm = (wid & 1) * 32, wn = (wid >> 1) * 64;
    long row0 = (long)blockIdx.x * 64;

    // ---- phase 1: A[e] = ns[src[e]] - (rare) backtrack rows, stored fp16 ----
    {
        int grp = tid >> 6;
        int t4  = (tid & 63) * 4;          // half index
        int tw  = (tid & 63) * 2;          // word index
#pragma unroll
        for (int ib = 0; ib < 16; ib += 4) {
            float4 v[4];
            int rrs[4];
#pragma unroll
            for (int u = 0; u < 4; u++) {
                int rr = grp + (ib + u) * 4;
                rrs[u] = rr;
                long e = row0 + rr;
                if (e < E) {
                    int sv = esrc[e];
                    v[u] = ldh4(g_ns, (long)sv * HDIM + t4);
                } else {
                    v[u] = make_float4(0, 0, 0, 0);
                }
            }
#pragma unroll
            for (int u = 0; u < 4; u++) {
                long e = row0 + rrs[u];
                if (e < E) {
                    int b0 = g_bt_ptr[e], b1 = g_bt_ptr[e + 1];
                    for (int j = b0; j < b1; j++) {
                        float4 w = ldh4(msg_in, (long)g_bt_idx[j] * HDIM + t4);
                        v[u].x -= w.x; v[u].y -= w.y; v[u].z -= w.z; v[u].w -= w.w;
                    }
                }
                uint2 st;
                st.x = f2h(make_float2(v[u].x, v[u].y));
                st.y = f2h(make_float2(v[u].z, v[u].w));
                *(uint2*)&As[rrs[u] * ASW + tw] = st;
            }
        }
    }

    float c[2][8][4];
#pragma unroll
    for (int mt = 0; mt < 2; mt++)
#pragma unroll
        for (int nt = 0; nt < 8; nt++)
#pragma unroll
            for (int r = 0; r < 4; r++) c[mt][nt][r] = 0.f;

    // preload B tile 0: 256 n-rows x 8 words (k 0..15); thread = one n-row
    {
        const uint4* src = (const uint4*)&g_Wht[(long)tid * 128];
        uint4 w0 = src[0], w1 = src[1];
        *(uint4*)&Bs[tid * BSW]     = w0;
        *(uint4*)&Bs[tid * BSW + 4] = w1;
    }
    __syncthreads();

    // ---- phase 2: GEMM over 16 k-tiles (one m16n8k16 per fragment set) ----
    for (int kt = 0; kt < 16; kt++) {
        uint4 pb0, pb1;
        if (kt < 15) {
            const uint4* src = (const uint4*)&g_Wht[(long)tid * 128 + (kt + 1) * 8];
            pb0 = src[0]; pb1 = src[1];
        }
        {
            int kb2 = kt * 8;
            unsigned a[2][4], b[8][2];
#pragma unroll
            for (int mt = 0; mt < 2; mt++) {
                int m0 = wm + mt * 16 + gg;
                a[mt][0] = As[m0 * ASW + kb2 + tig];
                a[mt][1] = As[(m0 + 8) * ASW + kb2 + tig];
                a[mt][2] = As[m0 * ASW + kb2 + tig + 4];
                a[mt][3] = As[(m0 + 8) * ASW + kb2 + tig + 4];
            }
#pragma unroll
            for (int nt = 0; nt < 8; nt++) {
                int n0 = wn + nt * 8 + gg;
                b[nt][0] = Bs[n0 * BSW + tig];
                b[nt][1] = Bs[n0 * BSW + tig + 4];
            }
#pragma unroll
            for (int mt = 0; mt < 2; mt++)
#pragma unroll
                for (int nt = 0; nt < 8; nt++)
                    mma_f16(c[mt][nt], a[mt], b[nt]);
        }
        if (kt < 15) {
            __syncthreads();
            *(uint4*)&Bs[tid * BSW]     = pb0;
            *(uint4*)&Bs[tid * BSW + 4] = pb1;
            __syncthreads();
        }
    }

    // ---- epilogue: msg_out = relu(msg_input + acc), stored fp16 ----
#pragma unroll
    for (int mt = 0; mt < 2; mt++) {
#pragma unroll
        for (int nt = 0; nt < 8; nt++) {
            int col = wn + nt * 8 + tig * 2;
            long r0 = row0 + wm + mt * 16 + gg;
            if (r0 < E) {
                float2 mi = *(const float2*)&g_msg_input[r0 * 256 + col];
                float2 o;
                o.x = fmaxf(mi.x + c[mt][nt][0], 0.f);
                o.y = fmaxf(mi.y + c[mt][nt][1], 0.f);
                msg_out[(r0 * 256 + col) >> 1] = f2h(o);
            }
            long r1 = r0 + 8;
            if (r1 < E) {
                float2 mi = *(const float2*)&g_msg_input[r1 * 256 + col];
                float2 o;
                o.x = fmaxf(mi.x + c[mt][nt][2], 0.f);
                o.y = fmaxf(mi.y + c[mt][nt][3], 0.f);
                msg_out[(r1 * 256 + col) >> 1] = f2h(o);
            }
        }
    }
}

// ---------------- tf32 GEMM kernels (edge input, output) ----------------
#define APAD 20
#define BPAD 264

__global__ __launch_bounds__(256)
void k_edge_tf32(const float* __restrict__ x_nodes, const float* __restrict__ x_edges,
                 const float* __restrict__ W_i, const int* __restrict__ esrc, int E) {
    __shared__ unsigned As[2][64][APAD];
    __shared__ unsigned Bs[2][16][BPAD];
    int tid = threadIdx.x;
    int lane = tid & 31, wid = tid >> 5;
    int gg = lane >> 2, tig = lane & 3;
    int wm = (wid & 1) * 32, wn = (wid >> 1) * 64;
    long row0 = (long)blockIdx.x * 64;

    float c[2][8][4];
#pragma unroll
    for (int mt = 0; mt < 2; mt++)
#pragma unroll
        for (int nt = 0; nt < 8; nt++)
#pragma unroll
            for (int r = 0; r < 4; r++) c[mt][nt][r] = 0.f;

    const int NT = 3;
    {
#pragma unroll
        for (int u = 0; u < 4; u++) {
            int i = tid + u * 256;
            int row = i >> 4, kk = i & 15;
            long r = row0 + row;
            float v = 0.f;
            if (r < E && kk < 40)
                v = (kk < 35) ? x_nodes[(long)esrc[r] * 35 + kk] : x_edges[r * 5 + (kk - 35)];
            As[0][row][kk] = f2tf(v);
        }
#pragma unroll
        for (int u = 0; u < 4; u++) {
            int ff = tid + u * 256, krow = ff >> 6, cc = ff & 63;
            float4 bvv = make_float4(0, 0, 0, 0);
            if (krow < 40) bvv = *(const float4*)&W_i[krow * 256 + cc * 4];
            unsigned* q = &Bs[0][krow][cc * 4];
            q[0] = f2tf(bvv.x); q[1] = f2tf(bvv.y); q[2] = f2tf(bvv.z); q[3] = f2tf(bvv.w);
        }
    }
    __syncthreads();

    for (int kt = 0; kt < NT; kt++) {
        int cbuf = kt & 1, nbuf = cbuf ^ 1;
        float avs[4]; float4 bv[4];
        if (kt < NT - 1) {
            int k0 = (kt + 1) * 16;
#pragma unroll
            for (int u = 0; u < 4; u++) {
                int i = tid + u * 256;
                int row = i >> 4, kk = i & 15;
                long r = row0 + row; int gk = k0 + kk;
                float v = 0.f;
                if (r < E && gk < 40)
                    v = (gk < 35) ? x_nodes[(long)esrc[r] * 35 + gk] : x_edges[r * 5 + (gk - 35)];
                avs[u] = v;
            }
#pragma unroll
            for (int u = 0; u < 4; u++) {
                int ff = tid + u * 256, krow = ff >> 6, cc = ff & 63;
                int gk = k0 + krow;
                bv[u] = make_float4(0, 0, 0, 0);
                if (gk < 40) bv[u] = *(const float4*)&W_i[gk * 256 + cc * 4];
            }
        }
#pragma unroll
        for (int ks = 0; ks < 16; ks += 8) {
            unsigned a[2][4], b[8][2];
#pragma unroll
            for (int mt = 0; mt < 2; mt++) {
                int m0 = wm + mt * 16 + gg;
                a[mt][0] = As[cbuf][m0][ks + tig];
                a[mt][1] = As[cbuf][m0 + 8][ks + tig];
                a[mt][2] = As[cbuf][m0][ks + tig + 4];
                a[mt][3] = As[cbuf][m0 + 8][ks + tig + 4];
            }
#pragma unroll
            for (int nt = 0; nt < 8; nt++) {
                int n0 = wn + nt * 8 + gg;
                b[nt][0] = Bs[cbuf][ks + tig][n0];
                b[nt][1] = Bs[cbuf][ks + tig + 4][n0];
            }
#pragma unroll
            for (int mt = 0; mt < 2; mt++)
#pragma unroll
                for (int nt = 0; nt < 8; nt++)
                    mma_tf32(c[mt][nt], a[mt], b[nt]);
        }
        if (kt < NT - 1) {
#pragma unroll
            for (int u = 0; u < 4; u++) {
                int i = tid + u * 256;
                int row = i >> 4, kk = i & 15;
                As[nbuf][row][kk] = f2tf(avs[u]);
            }
#pragma unroll
            for (int u = 0; u < 4; u++) {
                int ff = tid + u * 256, krow = ff >> 6, cc = ff & 63;
                unsigned* q = &Bs[nbuf][krow][cc * 4];
                q[0] = f2tf(bv[u].x); q[1] = f2tf(bv[u].y); q[2] = f2tf(bv[u].z); q[3] = f2tf(bv[u].w);
            }
        }
        __syncthreads();
    }

#pragma unroll
    for (int mt = 0; mt < 2; mt++) {
#pragma unroll
        for (int nt = 0; nt < 8; nt++) {
            int col = wn + nt * 8 + tig * 2;
            long r0 = row0 + wm + mt * 16 + gg;
            if (r0 < E) {
                float2 v = make_float2(c[mt][nt][0], c[mt][nt][1]);
                *(float2*)&g_msg_input[r0 * 256 + col] = v;
                g_msgA[(r0 * 256 + col) >> 1] = f2h(make_float2(fmaxf(v.x, 0.f), fmaxf(v.y, 0.f)));
            }
            long r1 = r0 + 8;
            if (r1 < E) {
                float2 v = make_float2(c[mt][nt][2], c[mt][nt][3]);
                *(float2*)&g_msg_input[r1 * 256 + col] = v;
                g_msgA[(r1 * 256 + col) >> 1] = f2h(make_float2(fmaxf(v.x, 0.f), fmaxf(v.y, 0.f)));
            }
        }
    }
}

__global__ __launch_bounds__(256)
void k_out_tf32(const float* __restrict__ x_nodes, const float* __restrict__ W_o,
                const float* __restrict__ b_o, int N) {
    __shared__ unsigned As[2][64][APAD];
    __shared__ unsigned Bs[2][16][BPAD];
    int tid = threadIdx.x;
    int lane = tid & 31, wid = tid >> 5;
    int gg = lane >> 2, tig = lane & 3;
    int wm = (wid & 1) * 32, wn = (wid >> 1) * 64;
    long row0 = (long)blockIdx.x * 64;

    float c[2][8][4];
#pragma unroll
    for (int mt = 0; mt < 2; mt++)
#pragma unroll
        for (int nt = 0; nt < 8; nt++)
#pragma unroll
            for (int r = 0; r < 4; r++) c[mt][nt][r] = 0.f;

    const int NT = 19;
    {
#pragma unroll
        for (int u = 0; u < 4; u++) {
            int i = tid + u * 256;
            int row = i >> 4, kk = i & 15;
            long r = row0 + row;
            float v = 0.f;
            if (r < N && kk < 291)
                v = (kk < 35) ? x_nodes[r * 35 + kk] : g_m[r * 256 + (kk - 35)];
            As[0][row][kk] = f2tf(v);
        }
#pragma unroll
        for (int u = 0; u < 4; u++) {
            int ff = tid + u * 256, krow = ff >> 6, cc = ff & 63;
            float4 bvv = make_float4(0, 0, 0, 0);
            if (krow < 291) bvv = *(const float4*)&W_o[krow * 256 + cc * 4];
            unsigned* q = &Bs[0][krow][cc * 4];
            q[0] = f2tf(bvv.x); q[1] = f2tf(bvv.y); q[2] = f2tf(bvv.z); q[3] = f2tf(bvv.w);
        }
    }
    __syncthreads();

    for (int kt = 0; kt < NT; kt++) {
        int cbuf = kt & 1, nbuf = cbuf ^ 1;
        float avs[4]; float4 bv[4];
        if (kt < NT - 1) {
            int k0 = (kt + 1) * 16;
#pragma unroll
            for (int u = 0; u < 4; u++) {
                int i = tid + u * 256;
                int row = i >> 4, kk = i & 15;
                long r = row0 + row; int gk = k0 + kk;
                float v = 0.f;
                if (r < N && gk < 291)
                    v = (gk < 35) ? x_nodes[r * 35 + gk] : g_m[r * 256 + (gk - 35)];
                avs[u] = v;
            }
#pragma unroll
            for (int u = 0; u < 4; u++) {
                int ff = tid + u * 256, krow = ff >> 6, cc = ff & 63;
                int gk = k0 + krow;
                bv[u] = make_float4(0, 0, 0, 0);
                if (gk < 291) bv[u] = *(const float4*)&W_o[gk * 256 + cc * 4];
            }
        }
#pragma unroll
        for (int ks = 0; ks < 16; ks += 8) {
            unsigned a[2][4], b[8][2];
#pragma unroll
            for (int mt = 0; mt < 2; mt++) {
                int m0 = wm + mt * 16 + gg;
                a[mt][0] = As[cbuf][m0][ks + tig];
                a[mt][1] = As[cbuf][m0 + 8][ks + tig];
                a[mt][2] = As[cbuf][m0][ks + tig + 4];
                a[mt][3] = As[cbuf][m0 + 8][ks + tig + 4];
            }
#pragma unroll
            for (int nt = 0; nt < 8; nt++) {
                int n0 = wn + nt * 8 + gg;
                b[nt][0] = Bs[cbuf][ks + tig][n0];
                b[nt][1] = Bs[cbuf][ks + tig + 4][n0];
            }
#pragma unroll
            for (int mt = 0; mt < 2; mt++)
#pragma unroll
                for (int nt = 0; nt < 8; nt++)
                    mma_tf32(c[mt][nt], a[mt], b[nt]);
        }
        if (kt < NT - 1) {
#pragma unroll
            for (int u = 0; u < 4; u++) {
                int i = tid + u * 256;
                int row = i >> 4, kk = i & 15;
                As[nbuf][row][kk] = f2tf(avs[u]);
            }
#pragma unroll
            for (int u = 0; u < 4; u++) {
                int ff = tid + u * 256, krow = ff >> 6, cc = ff & 63;
                unsigned* q = &Bs[nbuf][krow][cc * 4];
                q[0] = f2tf(bv[u].x); q[1] = f2tf(bv[u].y); q[2] = f2tf(bv[u].z); q[3] = f2tf(bv[u].w);
            }
        }
        __syncthreads();
    }

#pragma unroll
    for (int mt = 0; mt < 2; mt++) {
#pragma unroll
        for (int nt = 0; nt < 8; nt++) {
            int col = wn + nt * 8 + tig * 2;
            float b0v = b_o[col], b1v = b_o[col + 1];
            long r0 = row0 + wm + mt * 16 + gg;
            if (r0 < N) {
                float2 o;
                o.x = fmaxf(c[mt][nt][0] + b0v, 0.f);
                o.y = fmaxf(c[mt][nt][1] + b1v, 0.f);
                *(float2*)&g_h[r0 * 256 + col] = o;
            }
            long r1 = r0 + 8;
            if (r1 < N) {
                float2 o;
                o.x = fmaxf(c[mt][nt][2] + b0v, 0.f);
                o.y = fmaxf(c[mt][nt][3] + b1v, 0.f);
                *(float2*)&g_h[r1 * 256 + col] = o;
            }
        }
    }
}

// per-graph mean over sorted graph_ids
__global__ void k_mean(const int* __restrict__ gid, float* __restrict__ out, int N) {
    int g = blockIdx.x;
    int t = threadIdx.x;
    int lo = 0, hi = N;
    while (lo < hi) { int m = (lo + hi) >> 1; if (gid[m] < g) lo = m + 1; else hi = m; }
    int s = lo;
    hi = N;
    while (lo < hi) { int m = (lo + hi) >> 1; if (gid[m] < g + 1) lo = m + 1; else hi = m; }
    int e = lo;
    float sum = 0.f;
    for (int n = s; n < e; n++) sum += g_h[n * HDIM + t];
    float c = (float)((e - s) > 0 ? (e - s) : 1);
    out[g * HDIM + t] = sum / c;
}

// ---------------- launcher ----------------
extern "C" void kernel_launch(void* const* d_in, const int* in_sizes, int n_in,
                              void* d_out, int out_size) {
    const float* x_nodes = (const float*)d_in[0];
    const float* x_edges = (const float*)d_in[1];
    const float* tree_m  = (const float*)d_in[2];
    const float* W_i     = (const float*)d_in[3];
    const float* W_h     = (const float*)d_in[4];
    const float* W_o     = (const float*)d_in[5];
    const float* b_o     = (const float*)d_in[6];
    const int*   esrc    = (const int*)d_in[7];
    const int*   edst    = (const int*)d_in[8];
    const int*   tgt     = (const int*)d_in[11];
    const int*   teid    = (const int*)d_in[12];
    const int*   gid     = (const int*)d_in[13];

    int N = in_sizes[0] / 35;
    int E = in_sizes[1] / 5;
    int K = in_sizes[11];
    int G = out_size / HDIM;
    float* out = (float*)d_out;

    int* d_node_ptr; cudaGetSymbolAddress((void**)&d_node_ptr, g_node_ptr);
    int* d_bt_ptr;   cudaGetSymbolAddress((void**)&d_bt_ptr, g_bt_ptr);

    cudaFuncSetAttribute(k_bp_fused, cudaFuncAttributeMaxDynamicSharedMemorySize, BP_SMEM);

    // node in-edge CSR
    k_zero_cnt<<<(N + 255) / 256, 256>>>(N);
    k_count<<<(E + 255) / 256, 256>>>(edst, E);
    k_scan<<<1, 1024>>>(d_node_ptr, N, 1);
    k_place<<<(E + 255) / 256, 256>>>(edst, E);
    // backtrack CSR
    k_bt_count<<<(E + 255) / 256, 256>>>(esrc, edst, E);
    k_scan<<<1, 1024>>>(d_bt_ptr, E, 0);
    k_bt_fill<<<(E + 255) / 256, 256>>>(esrc, edst, E);

    k_convWt<<<(HDIM * HDIM / 2 + 255) / 256, 256>>>(W_h);
    k_zero_alpha<<<(N * HDIM + 255) / 256, 256>>>(N * HDIM);
    k_edge_tf32<<<(E + 63) / 64, 256>>>(x_nodes, x_edges, W_i, esrc, E);
    k_scatter_alpha<<<(K * 256 + 255) / 256, 256>>>(tree_m, tgt, teid, K);

    // it0: A->B ; it1: B->A ; it2: A->B ; final m from B
    k_nodesum<<<(N + 3) / 4, 256>>>(0, 0, N);
    k_bp_fused<<<(E + 63) / 64, 256, BP_SMEM>>>(esrc, E, 0);
    k_nodesum<<<(N + 3) / 4, 256>>>(1, 0, N);
    k_bp_fused<<<(E + 63) / 64, 256, BP_SMEM>>>(esrc, E, 1);
    k_nodesum<<<(N + 3) / 4, 256>>>(0, 0, N);
    k_bp_fused<<<(E + 63) / 64, 256, BP_SMEM>>>(esrc, E, 0);
    k_nodesum<<<(N + 3) / 4, 256>>>(1, 1, N);

    k_out_tf32<<<(N + 63) / 64, 256>>>(x_nodes, W_o, b_o, N);
    k_mean<<<G, 256>>>(gid, out, N);
}

// round 13
// speedup vs baseline: 1.3945x; 1.3945x over previous
#include <cuda_runtime.h>
#include <cuda_fp16.h>

#define HDIM 256
#define MAX_E 200000
#define MAX_N 50000
#define MAX_BT (MAX_E * 8)
#define BTCAP 2048

// ---------------- static scratch ----------------
__device__ float    g_msg_input[MAX_E * HDIM];
__device__ unsigned g_msgA[MAX_E * HDIM / 2];   // fp16 half2-packed
__device__ unsigned g_msgB[MAX_E * HDIM / 2];   // fp16 half2-packed
__device__ float    g_node_alpha[MAX_N * HDIM];
__device__ unsigned g_ns[MAX_N * HDIM / 2];     // fp16: alpha + in-edge msg sum
__device__ unsigned g_Z[MAX_N * HDIM / 2];      // fp16: ns @ W_h
__device__ float    g_btcorr[BTCAP * HDIM];     // per-bt-pair correction @ W_h
__device__ float    g_m[MAX_N * HDIM];
__device__ float    g_h[MAX_N * HDIM];
__device__ unsigned g_Wht[HDIM * HDIM / 2];     // W_h^T fp16: [n][k] half2-packed
__device__ int      g_cnt[MAX_E];
__device__ int      g_node_ptr[MAX_N + 1];
__device__ int      g_in_idx[MAX_E];
__device__ int      g_bt_ptr[MAX_E + 1];
__device__ int      g_bt_idx[MAX_BT];

// ---------------- helpers ----------------
__device__ __forceinline__ unsigned f2tf(float x) {
    unsigned u; asm("cvt.rna.tf32.f32 %0, %1;" : "=r"(u) : "f"(x)); return u;
}
__device__ __forceinline__ float2 h2f(unsigned u) {
    __half2 h = *reinterpret_cast<__half2*>(&u);
    return __half22float2(h);
}
__device__ __forceinline__ unsigned f2h(float2 v) {
    __half2 h = __float22half2_rn(v);
    return *reinterpret_cast<unsigned*>(&h);
}
__device__ __forceinline__ float4 ldh4(const unsigned* p, long idx) {  // idx multiple of 4 (halves)
    uint2 u = *(const uint2*)&p[idx >> 1];
    float2 a = h2f(u.x), b = h2f(u.y);
    return make_float4(a.x, a.y, b.x, b.y);
}
__device__ __forceinline__ void mma_tf32(float* c, const unsigned* a, const unsigned* b) {
    asm volatile(
        "mma.sync.aligned.m16n8k8.row.col.f32.tf32.tf32.f32 "
        "{%0,%1,%2,%3}, {%4,%5,%6,%7}, {%8,%9}, {%0,%1,%2,%3};\n"
        : "+f"(c[0]), "+f"(c[1]), "+f"(c[2]), "+f"(c[3])
        : "r"(a[0]), "r"(a[1]), "r"(a[2]), "r"(a[3]), "r"(b[0]), "r"(b[1]));
}
__device__ __forceinline__ void mma_f16(float* c, const unsigned* a, const unsigned* b) {
    asm volatile(
        "mma.sync.aligned.m16n8k16.row.col.f32.f16.f16.f32 "
        "{%0,%1,%2,%3}, {%4,%5,%6,%7}, {%8,%9}, {%0,%1,%2,%3};\n"
        : "+f"(c[0]), "+f"(c[1]), "+f"(c[2]), "+f"(c[3])
        : "r"(a[0]), "r"(a[1]), "r"(a[2]), "r"(a[3]), "r"(b[0]), "r"(b[1]));
}

// ---------------- CSR builds ----------------
__global__ void k_zero_cnt(int n) {
    int i = blockIdx.x * blockDim.x + threadIdx.x;
    if (i < n) g_cnt[i] = 0;
}
__global__ void k_count(const int* __restrict__ edst, int E) {
    int e = blockIdx.x * blockDim.x + threadIdx.x;
    if (e < E) atomicAdd(&g_cnt[edst[e]], 1);
}
__global__ void k_scan(int* __restrict__ ptr, int n, int rezero) {
    __shared__ int sh[1024];
    __shared__ int carry;
    int tid = threadIdx.x;
    if (tid == 0) { carry = 0; ptr[0] = 0; }
    __syncthreads();
    for (int base = 0; base < n; base += 1024) {
        int i = base + tid;
        int v = (i < n) ? g_cnt[i] : 0;
        sh[tid] = v; __syncthreads();
        for (int off = 1; off < 1024; off <<= 1) {
            int add = (tid >= off) ? sh[tid - off] : 0;
            __syncthreads();
            sh[tid] += add; __syncthreads();
        }
        if (i < n) { ptr[i + 1] = carry + sh[tid]; if (rezero) g_cnt[i] = 0; }
        __syncthreads();
        if (tid == 0) carry += sh[1023];
        __syncthreads();
    }
}
__global__ void k_place(const int* __restrict__ edst, int E) {
    int e = blockIdx.x * blockDim.x + threadIdx.x;
    if (e >= E) return;
    int v = edst[e];
    int pos = atomicAdd(&g_cnt[v], 1);
    g_in_idx[g_node_ptr[v] + pos] = e;
}
__global__ void k_bt_count(const int* __restrict__ esrc, const int* __restrict__ edst, int E) {
    int e = blockIdx.x * blockDim.x + threadIdx.x;
    if (e >= E) return;
    int sv = esrc[e], dv = edst[e];
    int cnt = 0;
    for (int j = g_node_ptr[sv]; j < g_node_ptr[sv + 1]; j++)
        if (esrc[g_in_idx[j]] == dv) cnt++;
    g_cnt[e] = cnt;
}
__global__ void k_bt_fill(const int* __restrict__ esrc, const int* __restrict__ edst, int E) {
    int e = blockIdx.x * blockDim.x + threadIdx.x;
    if (e >= E) return;
    int sv = esrc[e], dv = edst[e];
    int k = g_bt_ptr[e];
    for (int j = g_node_ptr[sv]; j < g_node_ptr[sv + 1]; j++) {
        int e2 = g_in_idx[j];
        if (esrc[e2] == dv && k < MAX_BT) g_bt_idx[k++] = e2;
    }
}

// ---------------- misc ----------------
__global__ void k_zero_alpha(int n) {
    int i = blockIdx.x * blockDim.x + threadIdx.x;
    if (i < n) g_node_alpha[i] = 0.f;
}
__global__ void k_scatter_alpha(const float* __restrict__ tree_m,
                                const int* __restrict__ tgt,
                                const int* __restrict__ teid, int K) {
    int i = blockIdx.x * blockDim.x + threadIdx.x;
    int k = i >> 8, h = i & 255;
    if (k >= K) return;
    atomicAdd(&g_node_alpha[tgt[k] * HDIM + h], tree_m[teid[k] * HDIM + h]);
}
// W_h^T fp16: g_Wht[n*128 + kw] = {W_h[2kw][n], W_h[2kw+1][n]}
__global__ void k_convWt(const float* __restrict__ W_h) {
    int i = blockIdx.x * blockDim.x + threadIdx.x;
    if (i >= HDIM * HDIM / 2) return;
    int n = i >> 7, kw = i & 127;
    float2 v = make_float2(W_h[(2 * kw) * HDIM + n], W_h[(2 * kw + 1) * HDIM + n]);
    g_Wht[i] = f2h(v);
}

// ---------------- per-node sum: out[v] = alpha[v] + sum msg_in[in(v)] ----------------
__global__ __launch_bounds__(256)
void k_nodesum(int buf, int to_m, int N) {
    const unsigned* __restrict__ msg_in = buf ? g_msgB : g_msgA;
    int v = blockIdx.x * 4 + (threadIdx.x >> 6);
    if (v >= N) return;
    int t4 = (threadIdx.x & 63) * 4;
    float4 acc = *(const float4*)&g_node_alpha[(long)v * HDIM + t4];
    int s = g_node_ptr[v], en = g_node_ptr[v + 1];
    int i = s;
    for (; i + 4 <= en; i += 4) {
        int i0 = g_in_idx[i], i1 = g_in_idx[i + 1], i2 = g_in_idx[i + 2], i3 = g_in_idx[i + 3];
        float4 v0 = ldh4(msg_in, (long)i0 * HDIM + t4);
        float4 v1 = ldh4(msg_in, (long)i1 * HDIM + t4);
        float4 v2 = ldh4(msg_in, (long)i2 * HDIM + t4);
        float4 v3 = ldh4(msg_in, (long)i3 * HDIM + t4);
        acc.x += v0.x + v1.x + v2.x + v3.x;
        acc.y += v0.y + v1.y + v2.y + v3.y;
        acc.z += v0.z + v1.z + v2.z + v3.z;
        acc.w += v0.w + v1.w + v2.w + v3.w;
    }
    for (; i < en; i++) {
        float4 vv = ldh4(msg_in, (long)g_in_idx[i] * HDIM + t4);
        acc.x += vv.x; acc.y += vv.y; acc.z += vv.z; acc.w += vv.w;
    }
    if (to_m) {
        *(float4*)&g_m[(long)v * HDIM + t4] = acc;
    } else {
        uint2 st;
        st.x = f2h(make_float2(acc.x, acc.y));
        st.y = f2h(make_float2(acc.z, acc.w));
        *(uint2*)&g_ns[((long)v * HDIM + t4) >> 1] = st;
    }
}

// ---------------- Z = ns @ W_h (per-node GEMM, fp16 MMA) ----------------
#define ASW 132
#define BSW 12
#define Z_SMEM ((64 * ASW + 256 * BSW) * 4)

__global__ __launch_bounds__(256, 2)
void k_Z(int N) {
    extern __shared__ unsigned smem_u[];
    unsigned* As = smem_u;             // [64][ASW] half2 words
    unsigned* Bs = smem_u + 64 * ASW;  // [256][BSW]

    int tid = threadIdx.x;
    int lane = tid & 31, wid = tid >> 5;
    int gg = lane >> 2, tig = lane & 3;
    int wm = (wid & 1) * 32, wn = (wid >> 1) * 64;
    long row0 = (long)blockIdx.x * 64;

    // A panel: contiguous copy of ns rows (uint4 = 8 halves)
    {
#pragma unroll
        for (int u = 0; u < 8; u++) {
            int i = tid + u * 256;        // 2048 uint4
            int row = i >> 5, w4 = (i & 31) * 4;
            long r = row0 + row;
            uint4 v = make_uint4(0, 0, 0, 0);
            if (r < N) v = *(const uint4*)&g_ns[(r << 7) + w4];
            *(uint4*)&As[row * ASW + w4] = v;
        }
    }
    // B tile 0
    {
        const uint4* src = (const uint4*)&g_Wht[(long)tid * 128];
        uint4 w0 = src[0], w1 = src[1];
        *(uint4*)&Bs[tid * BSW]     = w0;
        *(uint4*)&Bs[tid * BSW + 4] = w1;
    }

    float c[2][8][4];
#pragma unroll
    for (int mt = 0; mt < 2; mt++)
#pragma unroll
        for (int nt = 0; nt < 8; nt++)
#pragma unroll
            for (int r = 0; r < 4; r++) c[mt][nt][r] = 0.f;

    __syncthreads();

    for (int kt = 0; kt < 16; kt++) {
        uint4 pb0, pb1;
        if (kt < 15) {
            const uint4* src = (const uint4*)&g_Wht[(long)tid * 128 + (kt + 1) * 8];
            pb0 = src[0]; pb1 = src[1];
        }
        {
            int kb2 = kt * 8;
            unsigned a[2][4], b[8][2];
#pragma unroll
            for (int mt = 0; mt < 2; mt++) {
                int m0 = wm + mt * 16 + gg;
                a[mt][0] = As[m0 * ASW + kb2 + tig];
                a[mt][1] = As[(m0 + 8) * ASW + kb2 + tig];
                a[mt][2] = As[m0 * ASW + kb2 + tig + 4];
                a[mt][3] = As[(m0 + 8) * ASW + kb2 + tig + 4];
            }
#pragma unroll
            for (int nt = 0; nt < 8; nt++) {
                int n0 = wn + nt * 8 + gg;
                b[nt][0] = Bs[n0 * BSW + tig];
                b[nt][1] = Bs[n0 * BSW + tig + 4];
            }
#pragma unroll
            for (int mt = 0; mt < 2; mt++)
#pragma unroll
                for (int nt = 0; nt < 8; nt++)
                    mma_f16(c[mt][nt], a[mt], b[nt]);
        }
        if (kt < 15) {
            __syncthreads();
            *(uint4*)&Bs[tid * BSW]     = pb0;
            *(uint4*)&Bs[tid * BSW + 4] = pb1;
            __syncthreads();
        }
    }

    // epilogue: Z fp16
#pragma unroll
    for (int mt = 0; mt < 2; mt++) {
#pragma unroll
        for (int nt = 0; nt < 8; nt++) {
            int col = wn + nt * 8 + tig * 2;
            long r0 = row0 + wm + mt * 16 + gg;
            if (r0 < N)
                g_Z[(r0 * 256 + col) >> 1] = f2h(make_float2(c[mt][nt][0], c[mt][nt][1]));
            long r1 = r0 + 8;
            if (r1 < N)
                g_Z[(r1 * 256 + col) >> 1] = f2h(make_float2(c[mt][nt][2], c[mt][nt][3]));
        }
    }
}

// ---------------- rare backtrack corrections: corr[j] = msg_in[bt_idx[j]] @ W_h ----------------
__global__ __launch_bounds__(256)
void k_btcorr(int buf, int E) {
    const unsigned* __restrict__ msg_in = buf ? g_msgB : g_msgA;
    int j = blockIdx.x;
    int total = g_bt_ptr[E];
    if (j >= total) return;
    __shared__ unsigned sm[128];
    int tid = threadIdx.x;
    int e2 = g_bt_idx[j];
    if (tid < 128) sm[tid] = msg_in[(long)e2 * 128 + tid];
    __syncthreads();
    float acc = 0.f;
    const unsigned* wrow = &g_Wht[(long)tid * 128];
#pragma unroll 8
    for (int kw = 0; kw < 128; kw++) {
        float2 m = h2f(sm[kw]);
        float2 w = h2f(wrow[kw]);
        acc += m.x * w.x + m.y * w.y;
    }
    g_btcorr[(long)j * HDIM + tid] = acc;
}

// ---------------- apply: msg_out = relu(msg_input + Z[src] - btcorr) ----------------
__global__ __launch_bounds__(256)
void k_apply(const int* __restrict__ esrc, int E, int buf) {
    unsigned* __restrict__ msg_out = buf ? g_msgA : g_msgB;
    int e = blockIdx.x * 4 + (threadIdx.x >> 6);
    if (e >= E) return;
    int t4 = (threadIdx.x & 63) * 4;
    int sv = esrc[e];
    float4 z  = ldh4(g_Z, (long)sv * HDIM + t4);
    float4 mi = *(const float4*)&g_msg_input[(long)e * HDIM + t4];
    float4 acc = make_float4(mi.x + z.x, mi.y + z.y, mi.z + z.z, mi.w + z.w);
    int b0 = g_bt_ptr[e], b1 = g_bt_ptr[e + 1];
    for (int j = b0; j < b1 && j < BTCAP; j++) {
        float4 cr = *(const float4*)&g_btcorr[(long)j * HDIM + t4];
        acc.x -= cr.x; acc.y -= cr.y; acc.z -= cr.z; acc.w -= cr.w;
    }
    uint2 st;
    st.x = f2h(make_float2(fmaxf(acc.x, 0.f), fmaxf(acc.y, 0.f)));
    st.y = f2h(make_float2(fmaxf(acc.z, 0.f), fmaxf(acc.w, 0.f)));
    *(uint2*)&msg_out[((long)e * HDIM + t4) >> 1] = st;
}

// ---------------- tf32 GEMM kernels (edge input, output) ----------------
#define APAD 20
#define BPAD 264

__global__ __launch_bounds__(256)
void k_edge_tf32(const float* __restrict__ x_nodes, const float* __restrict__ x_edges,
                 const float* __restrict__ W_i, const int* __restrict__ esrc, int E) {
    __shared__ unsigned As[2][64][APAD];
    __shared__ unsigned Bs[2][16][BPAD];
    int tid = threadIdx.x;
    int lane = tid & 31, wid = tid >> 5;
    int gg = lane >> 2, tig = lane & 3;
    int wm = (wid & 1) * 32, wn = (wid >> 1) * 64;
    long row0 = (long)blockIdx.x * 64;

    float c[2][8][4];
#pragma unroll
    for (int mt = 0; mt < 2; mt++)
#pragma unroll
        for (int nt = 0; nt < 8; nt++)
#pragma unroll
            for (int r = 0; r < 4; r++) c[mt][nt][r] = 0.f;

    const int NT = 3;
    {
#pragma unroll
        for (int u = 0; u < 4; u++) {
            int i = tid + u * 256;
            int row = i >> 4, kk = i & 15;
            long r = row0 + row;
            float v = 0.f;
            if (r < E && kk < 40)
                v = (kk < 35) ? x_nodes[(long)esrc[r] * 35 + kk] : x_edges[r * 5 + (kk - 35)];
            As[0][row][kk] = f2tf(v);
        }
#pragma unroll
        for (int u = 0; u < 4; u++) {
            int ff = tid + u * 256, krow = ff >> 6, cc = ff & 63;
            float4 bvv = make_float4(0, 0, 0, 0);
            if (krow < 40) bvv = *(const float4*)&W_i[krow * 256 + cc * 4];
            unsigned* q = &Bs[0][krow][cc * 4];
            q[0] = f2tf(bvv.x); q[1] = f2tf(bvv.y); q[2] = f2tf(bvv.z); q[3] = f2tf(bvv.w);
        }
    }
    __syncthreads();

    for (int kt = 0; kt < NT; kt++) {
        int cbuf = kt & 1, nbuf = cbuf ^ 1;
        float avs[4]; float4 bv[4];
        if (kt < NT - 1) {
            int k0 = (kt + 1) * 16;
#pragma unroll
            for (int u = 0; u < 4; u++) {
                int i = tid + u * 256;
                int row = i >> 4, kk = i & 15;
                long r = row0 + row; int gk = k0 + kk;
                float v = 0.f;
                if (r < E && gk < 40)
                    v = (gk < 35) ? x_nodes[(long)esrc[r] * 35 + gk] : x_edges[r * 5 + (gk - 35)];
                avs[u] = v;
            }
#pragma unroll
            for (int u = 0; u < 4; u++) {
                int ff = tid + u * 256, krow = ff >> 6, cc = ff & 63;
                int gk = k0 + krow;
                bv[u] = make_float4(0, 0, 0, 0);
                if (gk < 40) bv[u] = *(const float4*)&W_i[gk * 256 + cc * 4];
            }
        }
#pragma unroll
        for (int ks = 0; ks < 16; ks += 8) {
            unsigned a[2][4], b[8][2];
#pragma unroll
            for (int mt = 0; mt < 2; mt++) {
                int m0 = wm + mt * 16 + gg;
                a[mt][0] = As[cbuf][m0][ks + tig];
                a[mt][1] = As[cbuf][m0 + 8][ks + tig];
                a[mt][2] = As[cbuf][m0][ks + tig + 4];
                a[mt][3] = As[cbuf][m0 + 8][ks + tig + 4];
            }
#pragma unroll
            for (int nt = 0; nt < 8; nt++) {
                int n0 = wn + nt * 8 + gg;
                b[nt][0] = Bs[cbuf][ks + tig][n0];
                b[nt][1] = Bs[cbuf][ks + tig + 4][n0];
            }
#pragma unroll
            for (int mt = 0; mt < 2; mt++)
#pragma unroll
                for (int nt = 0; nt < 8; nt++)
                    mma_tf32(c[mt][nt], a[mt], b[nt]);
        }
        if (kt < NT - 1) {
#pragma unroll
            for (int u = 0; u < 4; u++) {
                int i = tid + u * 256;
                int row = i >> 4, kk = i & 15;
                As[nbuf][row][kk] = f2tf(avs[u]);
            }
#pragma unroll
            for (int u = 0; u < 4; u++) {
                int ff = tid + u * 256, krow = ff >> 6, cc = ff & 63;
                unsigned* q = &Bs[nbuf][krow][cc * 4];
                q[0] = f2tf(bv[u].x); q[1] = f2tf(bv[u].y); q[2] = f2tf(bv[u].z); q[3] = f2tf(bv[u].w);
            }
        }
        __syncthreads();
    }

#pragma unroll
    for (int mt = 0; mt < 2; mt++) {
#pragma unroll
        for (int nt = 0; nt < 8; nt++) {
            int col = wn + nt * 8 + tig * 2;
            long r0 = row0 + wm + mt * 16 + gg;
            if (r0 < E) {
                float2 v = make_float2(c[mt][nt][0], c[mt][nt][1]);
                *(float2*)&g_msg_input[r0 * 256 + col] = v;
                g_msgA[(r0 * 256 + col) >> 1] = f2h(make_float2(fmaxf(v.x, 0.f), fmaxf(v.y, 0.f)));
            }
            long r1 = r0 + 8;
            if (r1 < E) {
                float2 v = make_float2(c[mt][nt][2], c[mt][nt][3]);
                *(float2*)&g_msg_input[r1 * 256 + col] = v;
                g_msgA[(r1 * 256 + col) >> 1] = f2h(make_float2(fmaxf(v.x, 0.f), fmaxf(v.y, 0.f)));
            }
        }
    }
}

__global__ __launch_bounds__(256)
void k_out_tf32(const float* __restrict__ x_nodes, const float* __restrict__ W_o,
                const float* __restrict__ b_o, int N) {
    __shared__ unsigned As[2][64][APAD];
    __shared__ unsigned Bs[2][16][BPAD];
    int tid = threadIdx.x;
    int lane = tid & 31, wid = tid >> 5;
    int gg = lane >> 2, tig = lane & 3;
    int wm = (wid & 1) * 32, wn = (wid >> 1) * 64;
    long row0 = (long)blockIdx.x * 64;

    float c[2][8][4];
#pragma unroll
    for (int mt = 0; mt < 2; mt++)
#pragma unroll
        for (int nt = 0; nt < 8; nt++)
#pragma unroll
            for (int r = 0; r < 4; r++) c[mt][nt][r] = 0.f;

    const int NT = 19;
    {
#pragma unroll
        for (int u = 0; u < 4; u++) {
            int i = tid + u * 256;
            int row = i >> 4, kk = i & 15;
            long r = row0 + row;
            float v = 0.f;
            if (r < N && kk < 291)
                v = (kk < 35) ? x_nodes[r * 35 + kk] : g_m[r * 256 + (kk - 35)];
            As[0][row][kk] = f2tf(v);
        }
#pragma unroll
        for (int u = 0; u < 4; u++) {
            int ff = tid + u * 256, krow = ff >> 6, cc = ff & 63;
            float4 bvv = make_float4(0, 0, 0, 0);
            if (krow < 291) bvv = *(const float4*)&W_o[krow * 256 + cc * 4];
            unsigned* q = &Bs[0][krow][cc * 4];
            q[0] = f2tf(bvv.x); q[1] = f2tf(bvv.y); q[2] = f2tf(bvv.z); q[3] = f2tf(bvv.w);
        }
    }
    __syncthreads();

    for (int kt = 0; kt < NT; kt++) {
        int cbuf = kt & 1, nbuf = cbuf ^ 1;
        float avs[4]; float4 bv[4];
        if (kt < NT - 1) {
            int k0 = (kt + 1) * 16;
#pragma unroll
            for (int u = 0; u < 4; u++) {
                int i = tid + u * 256;
                int row = i >> 4, kk = i & 15;
                long r = row0 + row; int gk = k0 + kk;
                float v = 0.f;
                if (r < N && gk < 291)
                    v = (gk < 35) ? x_nodes[r * 35 + gk] : g_m[r * 256 + (gk - 35)];
                avs[u] = v;
            }
#pragma unroll
            for (int u = 0; u < 4; u++) {
                int ff = tid + u * 256, krow = ff >> 6, cc = ff & 63;
                int gk = k0 + krow;
                bv[u] = make_float4(0, 0, 0, 0);
                if (gk < 291) bv[u] = *(const float4*)&W_o[gk * 256 + cc * 4];
            }
        }
#pragma unroll
        for (int ks = 0; ks < 16; ks += 8) {
            unsigned a[2][4], b[8][2];
#pragma unroll
            for (int mt = 0; mt < 2; mt++) {
                int m0 = wm + mt * 16 + gg;
                a[mt][0] = As[cbuf][m0][ks + tig];
                a[mt][1] = As[cbuf][m0 + 8][ks + tig];
                a[mt][2] = As[cbuf][m0][ks + tig + 4];
                a[mt][3] = As[cbuf][m0 + 8][ks + tig + 4];
            }
#pragma unroll
            for (int nt = 0; nt < 8; nt++) {
                int n0 = wn + nt * 8 + gg;
                b[nt][0] = Bs[cbuf][ks + tig][n0];
                b[nt][1] = Bs[cbuf][ks + tig + 4][n0];
            }
#pragma unroll
            for (int mt = 0; mt < 2; mt++)
#pragma unroll
                for (int nt = 0; nt < 8; nt++)
                    mma_tf32(c[mt][nt], a[mt], b[nt]);
        }
        if (kt < NT - 1) {
#pragma unroll
            for (int u = 0; u < 4; u++) {
                int i = tid + u * 256;
                int row = i >> 4, kk = i & 15;
                As[nbuf][row][kk] = f2tf(avs[u]);
            }
#pragma unroll
            for (int u = 0; u < 4; u++) {
                int ff = tid + u * 256, krow = ff >> 6, cc = ff & 63;
                unsigned* q = &Bs[nbuf][krow][cc * 4];
                q[0] = f2tf(bv[u].x); q[1] = f2tf(bv[u].y); q[2] = f2tf(bv[u].z); q[3] = f2tf(bv[u].w);
            }
        }
        __syncthreads();
    }

#pragma unroll
    for (int mt = 0; mt < 2; mt++) {
#pragma unroll
        for (int nt = 0; nt < 8; nt++) {
            int col = wn + nt * 8 + tig * 2;
            float b0v = b_o[col], b1v = b_o[col + 1];
            long r0 = row0 + wm + mt * 16 + gg;
            if (r0 < N) {
                float2 o;
                o.x = fmaxf(c[mt][nt][0] + b0v, 0.f);
                o.y = fmaxf(c[mt][nt][1] + b1v, 0.f);
                *(float2*)&g_h[r0 * 256 + col] = o;
            }
            long r1 = r0 + 8;
            if (r1 < N) {
                float2 o;
                o.x = fmaxf(c[mt][nt][2] + b0v, 0.f);
                o.y = fmaxf(c[mt][nt][3] + b1v, 0.f);
                *(float2*)&g_h[r1 * 256 + col] = o;
            }
        }
    }
}

// per-graph mean over sorted graph_ids
__global__ void k_mean(const int* __restrict__ gid, float* __restrict__ out, int N) {
    int g = blockIdx.x;
    int t = threadIdx.x;
    int lo = 0, hi = N;
    while (lo < hi) { int m = (lo + hi) >> 1; if (gid[m] < g) lo = m + 1; else hi = m; }
    int s = lo;
    hi = N;
    while (lo < hi) { int m = (lo + hi) >> 1; if (gid[m] < g + 1) lo = m + 1; else hi = m; }
    int e = lo;
    float sum = 0.f;
    for (int n = s; n < e; n++) sum += g_h[n * HDIM + t];
    float c = (float)((e - s) > 0 ? (e - s) : 1);
    out[g * HDIM + t] = sum / c;
}

// ---------------- launcher ----------------
extern "C" void kernel_launch(void* const* d_in, const int* in_sizes, int n_in,
                              void* d_out, int out_size) {
    const float* x_nodes = (const float*)d_in[0];
    const float* x_edges = (const float*)d_in[1];
    const float* tree_m  = (const float*)d_in[2];
    const float* W_i     = (const float*)d_in[3];
    const float* W_h     = (const float*)d_in[4];
    const float* W_o     = (const float*)d_in[5];
    const float* b_o     = (const float*)d_in[6];
    const int*   esrc    = (const int*)d_in[7];
    const int*   edst    = (const int*)d_in[8];
    const int*   tgt     = (const int*)d_in[11];
    const int*   teid    = (const int*)d_in[12];
    const int*   gid     = (const int*)d_in[13];

    int N = in_sizes[0] / 35;
    int E = in_sizes[1] / 5;
    int K = in_sizes[11];
    int G = out_size / HDIM;
    float* out = (float*)d_out;

    int* d_node_ptr; cudaGetSymbolAddress((void**)&d_node_ptr, g_node_ptr);
    int* d_bt_ptr;   cudaGetSymbolAddress((void**)&d_bt_ptr, g_bt_ptr);

    cudaFuncSetAttribute(k_Z, cudaFuncAttributeMaxDynamicSharedMemorySize, Z_SMEM);

    // node in-edge CSR
    k_zero_cnt<<<(N + 255) / 256, 256>>>(N);
    k_count<<<(E + 255) / 256, 256>>>(edst, E);
    k_scan<<<1, 1024>>>(d_node_ptr, N, 1);
    k_place<<<(E + 255) / 256, 256>>>(edst, E);
    // backtrack CSR
    k_bt_count<<<(E + 255) / 256, 256>>>(esrc, edst, E);
    k_scan<<<1, 1024>>>(d_bt_ptr, E, 0);
    k_bt_fill<<<(E + 255) / 256, 256>>>(esrc, edst, E);

    k_convWt<<<(HDIM * HDIM / 2 + 255) / 256, 256>>>(W_h);
    k_zero_alpha<<<(N * HDIM + 255) / 256, 256>>>(N * HDIM);
    k_edge_tf32<<<(E + 63) / 64, 256>>>(x_nodes, x_edges, W_i, esrc, E);
    k_scatter_alpha<<<(K * 256 + 255) / 256, 256>>>(tree_m, tgt, teid, K);

    // BP iterations: msgA -> msgB -> msgA -> msgB ; final m from msgB
    for (int it = 0; it < 3; it++) {
        int buf = it & 1;             // 0: A->B, 1: B->A
        k_nodesum<<<(N + 3) / 4, 256>>>(buf, 0, N);
        k_Z<<<(N + 63) / 64, 256, Z_SMEM>>>(N);
        k_btcorr<<<BTCAP, 256>>>(buf, E);
        k_apply<<<(E + 3) / 4, 256>>>(esrc, E, buf);
    }
    k_nodesum<<<(N + 3) / 4, 256>>>(1, 1, N);   // final m from msgB

    k_out_tf32<<<(N + 63) / 64, 256>>>(x_nodes, W_o, b_o, N);
    k_mean<<<G, 256>>>(gid, out, N);
}

// round 14
// speedup vs baseline: 1.6077x; 1.1528x over previous
#include <cuda_runtime.h>
#include <cuda_fp16.h>

#define HDIM 256
#define MAX_E 200000
#define MAX_N 50000
#define MAX_BT (MAX_E * 8)
#define BTCAP 2048

// ---------------- static scratch ----------------
__device__ unsigned g_msg_input[MAX_E * HDIM / 2];  // fp16 pre-activation
__device__ float    g_node_alpha[MAX_N * HDIM];
__device__ unsigned g_ns[MAX_N * HDIM / 2];         // fp16: alpha + in-edge msg sum
__device__ unsigned g_Z[MAX_N * HDIM / 2];          // fp16: ns @ W_h
__device__ float    g_btcorrA[BTCAP * HDIM];        // corr ping-pong
__device__ float    g_btcorrB[BTCAP * HDIM];
__device__ float    g_m[MAX_N * HDIM];
__device__ float    g_h[MAX_N * HDIM];
__device__ unsigned g_Wht[HDIM * HDIM / 2];         // W_h^T fp16: [n][k]
__device__ int      g_cnt[MAX_E];
__device__ int      g_node_ptr[MAX_N + 1];
__device__ int      g_in_idx[MAX_E];
__device__ int      g_bt_ptr[MAX_E + 1];
__device__ int      g_bt_idx[MAX_BT];

// ---------------- helpers ----------------
__device__ __forceinline__ unsigned f2tf(float x) {
    unsigned u; asm("cvt.rna.tf32.f32 %0, %1;" : "=r"(u) : "f"(x)); return u;
}
__device__ __forceinline__ float2 h2f(unsigned u) {
    __half2 h = *reinterpret_cast<__half2*>(&u);
    return __half22float2(h);
}
__device__ __forceinline__ unsigned f2h(float2 v) {
    __half2 h = __float22half2_rn(v);
    return *reinterpret_cast<unsigned*>(&h);
}
__device__ __forceinline__ float4 ldh4(const unsigned* p, long idx) {  // idx multiple of 4 (halves)
    uint2 u = *(const uint2*)&p[idx >> 1];
    float2 a = h2f(u.x), b = h2f(u.y);
    return make_float4(a.x, a.y, b.x, b.y);
}
__device__ __forceinline__ void mma_tf32(float* c, const unsigned* a, const unsigned* b) {
    asm volatile(
        "mma.sync.aligned.m16n8k8.row.col.f32.tf32.tf32.f32 "
        "{%0,%1,%2,%3}, {%4,%5,%6,%7}, {%8,%9}, {%0,%1,%2,%3};\n"
        : "+f"(c[0]), "+f"(c[1]), "+f"(c[2]), "+f"(c[3])
        : "r"(a[0]), "r"(a[1]), "r"(a[2]), "r"(a[3]), "r"(b[0]), "r"(b[1]));
}
__device__ __forceinline__ void mma_f16(float* c, const unsigned* a, const unsigned* b) {
    asm volatile(
        "mma.sync.aligned.m16n8k16.row.col.f32.f16.f16.f32 "
        "{%0,%1,%2,%3}, {%4,%5,%6,%7}, {%8,%9}, {%0,%1,%2,%3};\n"
        : "+f"(c[0]), "+f"(c[1]), "+f"(c[2]), "+f"(c[3])
        : "r"(a[0]), "r"(a[1]), "r"(a[2]), "r"(a[3]), "r"(b[0]), "r"(b[1]));
}

// ---------------- CSR builds ----------------
__global__ void k_zero_cnt(int n) {
    int i = blockIdx.x * blockDim.x + threadIdx.x;
    if (i < n) g_cnt[i] = 0;
}
__global__ void k_count(const int* __restrict__ edst, int E) {
    int e = blockIdx.x * blockDim.x + threadIdx.x;
    if (e < E) atomicAdd(&g_cnt[edst[e]], 1);
}
__global__ void k_scan(int* __restrict__ ptr, int n, int rezero) {
    __shared__ int sh[1024];
    __shared__ int carry;
    int tid = threadIdx.x;
    if (tid == 0) { carry = 0; ptr[0] = 0; }
    __syncthreads();
    for (int base = 0; base < n; base += 1024) {
        int i = base + tid;
        int v = (i < n) ? g_cnt[i] : 0;
        sh[tid] = v; __syncthreads();
        for (int off = 1; off < 1024; off <<= 1) {
            int add = (tid >= off) ? sh[tid - off] : 0;
            __syncthreads();
            sh[tid] += add; __syncthreads();
        }
        if (i < n) { ptr[i + 1] = carry + sh[tid]; if (rezero) g_cnt[i] = 0; }
        __syncthreads();
        if (tid == 0) carry += sh[1023];
        __syncthreads();
    }
}
__global__ void k_place(const int* __restrict__ edst, int E) {
    int e = blockIdx.x * blockDim.x + threadIdx.x;
    if (e >= E) return;
    int v = edst[e];
    int pos = atomicAdd(&g_cnt[v], 1);
    g_in_idx[g_node_ptr[v] + pos] = e;
}
__global__ void k_bt_count(const int* __restrict__ esrc, const int* __restrict__ edst, int E) {
    int e = blockIdx.x * blockDim.x + threadIdx.x;
    if (e >= E) return;
    int sv = esrc[e], dv = edst[e];
    int cnt = 0;
    for (int j = g_node_ptr[sv]; j < g_node_ptr[sv + 1]; j++)
        if (esrc[g_in_idx[j]] == dv) cnt++;
    g_cnt[e] = cnt;
}
__global__ void k_bt_fill(const int* __restrict__ esrc, const int* __restrict__ edst, int E) {
    int e = blockIdx.x * blockDim.x + threadIdx.x;
    if (e >= E) return;
    int sv = esrc[e], dv = edst[e];
    int k = g_bt_ptr[e];
    for (int j = g_node_ptr[sv]; j < g_node_ptr[sv + 1]; j++) {
        int e2 = g_in_idx[j];
        if (esrc[e2] == dv && k < MAX_BT) g_bt_idx[k++] = e2;
    }
}

// ---------------- misc ----------------
__global__ void k_zero_alpha(int n) {
    int i = blockIdx.x * blockDim.x + threadIdx.x;
    if (i < n) g_node_alpha[i] = 0.f;
}
__global__ void k_scatter_alpha(const float* __restrict__ tree_m,
                                const int* __restrict__ tgt,
                                const int* __restrict__ teid, int K) {
    int i = blockIdx.x * blockDim.x + threadIdx.x;
    int k = i >> 8, h = i & 255;
    if (k >= K) return;
    atomicAdd(&g_node_alpha[tgt[k] * HDIM + h], tree_m[teid[k] * HDIM + h]);
}
__global__ void k_convWt(const float* __restrict__ W_h) {
    int i = blockIdx.x * blockDim.x + threadIdx.x;
    if (i >= HDIM * HDIM / 2) return;
    int n = i >> 7, kw = i & 127;
    float2 v = make_float2(W_h[(2 * kw) * HDIM + n], W_h[(2 * kw + 1) * HDIM + n]);
    g_Wht[i] = f2h(v);
}

// ---------------- fused nodesum: ns_t[v] = alpha[v] + sum_in(v) msg_t[e] ----------------
// msg_t[e] = relu(msg_input[e] + (first?0:Z_prev[src[e]] - sum bt corr_prev))
__global__ __launch_bounds__(256)
void k_nodesum_f(const int* __restrict__ esrc, int first, int to_m, int N, int prevbuf) {
    const float* __restrict__ corrp = prevbuf ? g_btcorrB : g_btcorrA;
    int v = blockIdx.x * 4 + (threadIdx.x >> 6);
    if (v >= N) return;
    int t4 = (threadIdx.x & 63) * 4;
    float4 acc = *(const float4*)&g_node_alpha[(long)v * HDIM + t4];
    int s = g_node_ptr[v], en = g_node_ptr[v + 1];
    int i = s;
    for (; i + 4 <= en; i += 4) {
        int e0 = g_in_idx[i], e1 = g_in_idx[i + 1], e2 = g_in_idx[i + 2], e3 = g_in_idx[i + 3];
        float4 m0 = ldh4(g_msg_input, (long)e0 * HDIM + t4);
        float4 m1 = ldh4(g_msg_input, (long)e1 * HDIM + t4);
        float4 m2 = ldh4(g_msg_input, (long)e2 * HDIM + t4);
        float4 m3 = ldh4(g_msg_input, (long)e3 * HDIM + t4);
        if (!first) {
            int s0 = esrc[e0], s1 = esrc[e1], s2 = esrc[e2], s3 = esrc[e3];
            float4 z0 = ldh4(g_Z, (long)s0 * HDIM + t4);
            float4 z1 = ldh4(g_Z, (long)s1 * HDIM + t4);
            float4 z2 = ldh4(g_Z, (long)s2 * HDIM + t4);
            float4 z3 = ldh4(g_Z, (long)s3 * HDIM + t4);
            m0.x += z0.x; m0.y += z0.y; m0.z += z0.z; m0.w += z0.w;
            m1.x += z1.x; m1.y += z1.y; m1.z += z1.z; m1.w += z1.w;
            m2.x += z2.x; m2.y += z2.y; m2.z += z2.z; m2.w += z2.w;
            m3.x += z3.x; m3.y += z3.y; m3.z += z3.z; m3.w += z3.w;
            float4* ms[4] = {&m0, &m1, &m2, &m3};
            int es[4] = {e0, e1, e2, e3};
#pragma unroll
            for (int u = 0; u < 4; u++) {
                int b0 = g_bt_ptr[es[u]], b1 = g_bt_ptr[es[u] + 1];
                for (int j = b0; j < b1 && j < BTCAP; j++) {
                    float4 cr = *(const float4*)&corrp[(long)j * HDIM + t4];
                    ms[u]->x -= cr.x; ms[u]->y -= cr.y; ms[u]->z -= cr.z; ms[u]->w -= cr.w;
                }
            }
        }
        acc.x += fmaxf(m0.x, 0.f) + fmaxf(m1.x, 0.f) + fmaxf(m2.x, 0.f) + fmaxf(m3.x, 0.f);
        acc.y += fmaxf(m0.y, 0.f) + fmaxf(m1.y, 0.f) + fmaxf(m2.y, 0.f) + fmaxf(m3.y, 0.f);
        acc.z += fmaxf(m0.z, 0.f) + fmaxf(m1.z, 0.f) + fmaxf(m2.z, 0.f) + fmaxf(m3.z, 0.f);
        acc.w += fmaxf(m0.w, 0.f) + fmaxf(m1.w, 0.f) + fmaxf(m2.w, 0.f) + fmaxf(m3.w, 0.f);
    }
    for (; i < en; i++) {
        int e = g_in_idx[i];
        float4 m = ldh4(g_msg_input, (long)e * HDIM + t4);
        if (!first) {
            float4 z = ldh4(g_Z, (long)esrc[e] * HDIM + t4);
            m.x += z.x; m.y += z.y; m.z += z.z; m.w += z.w;
            int b0 = g_bt_ptr[e], b1 = g_bt_ptr[e + 1];
            for (int j = b0; j < b1 && j < BTCAP; j++) {
                float4 cr = *(const float4*)&corrp[(long)j * HDIM + t4];
                m.x -= cr.x; m.y -= cr.y; m.z -= cr.z; m.w -= cr.w;
            }
        }
        acc.x += fmaxf(m.x, 0.f); acc.y += fmaxf(m.y, 0.f);
        acc.z += fmaxf(m.z, 0.f); acc.w += fmaxf(m.w, 0.f);
    }
    if (to_m) {
        *(float4*)&g_m[(long)v * HDIM + t4] = acc;
    } else {
        uint2 st;
        st.x = f2h(make_float2(acc.x, acc.y));
        st.y = f2h(make_float2(acc.z, acc.w));
        *(uint2*)&g_ns[((long)v * HDIM + t4) >> 1] = st;
    }
}

// ---------------- Z = ns @ W_h (per-node GEMM, fp16 MMA) ----------------
#define ASW 132
#define BSW 12
#define Z_SMEM ((64 * ASW + 256 * BSW) * 4)

__global__ __launch_bounds__(256, 2)
void k_Z(int N) {
    extern __shared__ unsigned smem_u[];
    unsigned* As = smem_u;
    unsigned* Bs = smem_u + 64 * ASW;

    int tid = threadIdx.x;
    int lane = tid & 31, wid = tid >> 5;
    int gg = lane >> 2, tig = lane & 3;
    int wm = (wid & 1) * 32, wn = (wid >> 1) * 64;
    long row0 = (long)blockIdx.x * 64;

    {
#pragma unroll
        for (int u = 0; u < 8; u++) {
            int i = tid + u * 256;
            int row = i >> 5, w4 = (i & 31) * 4;
            long r = row0 + row;
            uint4 v = make_uint4(0, 0, 0, 0);
            if (r < N) v = *(const uint4*)&g_ns[(r << 7) + w4];
            *(uint4*)&As[row * ASW + w4] = v;
        }
    }
    {
        const uint4* src = (const uint4*)&g_Wht[(long)tid * 128];
        uint4 w0 = src[0], w1 = src[1];
        *(uint4*)&Bs[tid * BSW]     = w0;
        *(uint4*)&Bs[tid * BSW + 4] = w1;
    }

    float c[2][8][4];
#pragma unroll
    for (int mt = 0; mt < 2; mt++)
#pragma unroll
        for (int nt = 0; nt < 8; nt++)
#pragma unroll
            for (int r = 0; r < 4; r++) c[mt][nt][r] = 0.f;

    __syncthreads();

    for (int kt = 0; kt < 16; kt++) {
        uint4 pb0, pb1;
        if (kt < 15) {
            const uint4* src = (const uint4*)&g_Wht[(long)tid * 128 + (kt + 1) * 8];
            pb0 = src[0]; pb1 = src[1];
        }
        {
            int kb2 = kt * 8;
            unsigned a[2][4], b[8][2];
#pragma unroll
            for (int mt = 0; mt < 2; mt++) {
                int m0 = wm + mt * 16 + gg;
                a[mt][0] = As[m0 * ASW + kb2 + tig];
                a[mt][1] = As[(m0 + 8) * ASW + kb2 + tig];
                a[mt][2] = As[m0 * ASW + kb2 + tig + 4];
                a[mt][3] = As[(m0 + 8) * ASW + kb2 + tig + 4];
            }
#pragma unroll
            for (int nt = 0; nt < 8; nt++) {
                int n0 = wn + nt * 8 + gg;
                b[nt][0] = Bs[n0 * BSW + tig];
                b[nt][1] = Bs[n0 * BSW + tig + 4];
            }
#pragma unroll
            for (int mt = 0; mt < 2; mt++)
#pragma unroll
                for (int nt = 0; nt < 8; nt++)
                    mma_f16(c[mt][nt], a[mt], b[nt]);
        }
        if (kt < 15) {
            __syncthreads();
            *(uint4*)&Bs[tid * BSW]     = pb0;
            *(uint4*)&Bs[tid * BSW + 4] = pb1;
            __syncthreads();
        }
    }

#pragma unroll
    for (int mt = 0; mt < 2; mt++) {
#pragma unroll
        for (int nt = 0; nt < 8; nt++) {
            int col = wn + nt * 8 + tig * 2;
            long r0 = row0 + wm + mt * 16 + gg;
            if (r0 < N)
                g_Z[(r0 * 256 + col) >> 1] = f2h(make_float2(c[mt][nt][0], c[mt][nt][1]));
            long r1 = r0 + 8;
            if (r1 < N)
                g_Z[(r1 * 256 + col) >> 1] = f2h(make_float2(c[mt][nt][2], c[mt][nt][3]));
        }
    }
}

// ---------------- backtrack corrections: corr_t[j] = msg_t[bt_idx[j]] @ W_h ----------------
__global__ __launch_bounds__(256)
void k_btcorr(const int* __restrict__ esrc, int E, int first, int prevbuf, int curbuf) {
    const float* __restrict__ corrp = prevbuf ? g_btcorrB : g_btcorrA;
    float* __restrict__ corrc = curbuf ? g_btcorrB : g_btcorrA;
    int j = blockIdx.x;
    int total = g_bt_ptr[E];
    if (j >= total || j >= BTCAP) return;
    __shared__ unsigned sm[128];
    int tid = threadIdx.x;
    int e2 = g_bt_idx[j];
    if (tid < 128) {
        float2 m = h2f(g_msg_input[(long)e2 * 128 + tid]);
        if (!first) {
            float2 z = h2f(g_Z[(long)esrc[e2] * 128 + tid]);
            m.x += z.x; m.y += z.y;
            int b0 = g_bt_ptr[e2], b1 = g_bt_ptr[e2 + 1];
            for (int jj = b0; jj < b1 && jj < BTCAP; jj++) {
                m.x -= corrp[(long)jj * HDIM + tid * 2];
                m.y -= corrp[(long)jj * HDIM + tid * 2 + 1];
            }
        }
        m.x = fmaxf(m.x, 0.f); m.y = fmaxf(m.y, 0.f);
        sm[tid] = f2h(m);
    }
    __syncthreads();
    float acc = 0.f;
    const unsigned* wrow = &g_Wht[(long)tid * 128];
#pragma unroll 8
    for (int kw = 0; kw < 128; kw++) {
        float2 m = h2f(sm[kw]);
        float2 w = h2f(wrow[kw]);
        acc += m.x * w.x + m.y * w.y;
    }
    corrc[(long)j * HDIM + tid] = acc;
}

// ---------------- tf32 GEMM kernels (edge input, output) ----------------
#define APAD 20
#define BPAD 264

__global__ __launch_bounds__(256)
void k_edge_tf32(const float* __restrict__ x_nodes, const float* __restrict__ x_edges,
                 const float* __restrict__ W_i, const int* __restrict__ esrc, int E) {
    __shared__ unsigned As[2][64][APAD];
    __shared__ unsigned Bs[2][16][BPAD];
    int tid = threadIdx.x;
    int lane = tid & 31, wid = tid >> 5;
    int gg = lane >> 2, tig = lane & 3;
    int wm = (wid & 1) * 32, wn = (wid >> 1) * 64;
    long row0 = (long)blockIdx.x * 64;

    float c[2][8][4];
#pragma unroll
    for (int mt = 0; mt < 2; mt++)
#pragma unroll
        for (int nt = 0; nt < 8; nt++)
#pragma unroll
            for (int r = 0; r < 4; r++) c[mt][nt][r] = 0.f;

    const int NT = 3;
    {
#pragma unroll
        for (int u = 0; u < 4; u++) {
            int i = tid + u * 256;
            int row = i >> 4, kk = i & 15;
            long r = row0 + row;
            float v = 0.f;
            if (r < E && kk < 40)
                v = (kk < 35) ? x_nodes[(long)esrc[r] * 35 + kk] : x_edges[r * 5 + (kk - 35)];
            As[0][row][kk] = f2tf(v);
        }
#pragma unroll
        for (int u = 0; u < 4; u++) {
            int ff = tid + u * 256, krow = ff >> 6, cc = ff & 63;
            float4 bvv = make_float4(0, 0, 0, 0);
            if (krow < 40) bvv = *(const float4*)&W_i[krow * 256 + cc * 4];
            unsigned* q = &Bs[0][krow][cc * 4];
            q[0] = f2tf(bvv.x); q[1] = f2tf(bvv.y); q[2] = f2tf(bvv.z); q[3] = f2tf(bvv.w);
        }
    }
    __syncthreads();

    for (int kt = 0; kt < NT; kt++) {
        int cbuf = kt & 1, nbuf = cbuf ^ 1;
        float avs[4]; float4 bv[4];
        if (kt < NT - 1) {
            int k0 = (kt + 1) * 16;
#pragma unroll
            for (int u = 0; u < 4; u++) {
                int i = tid + u * 256;
                int row = i >> 4, kk = i & 15;
                long r = row0 + row; int gk = k0 + kk;
                float v = 0.f;
                if (r < E && gk < 40)
                    v = (gk < 35) ? x_nodes[(long)esrc[r] * 35 + gk] : x_edges[r * 5 + (gk - 35)];
                avs[u] = v;
            }
#pragma unroll
            for (int u = 0; u < 4; u++) {
                int ff = tid + u * 256, krow = ff >> 6, cc = ff & 63;
                int gk = k0 + krow;
                bv[u] = make_float4(0, 0, 0, 0);
                if (gk < 40) bv[u] = *(const float4*)&W_i[gk * 256 + cc * 4];
            }
        }
#pragma unroll
        for (int ks = 0; ks < 16; ks += 8) {
            unsigned a[2][4], b[8][2];
#pragma unroll
            for (int mt = 0; mt < 2; mt++) {
                int m0 = wm + mt * 16 + gg;
                a[mt][0] = As[cbuf][m0][ks + tig];
                a[mt][1] = As[cbuf][m0 + 8][ks + tig];
                a[mt][2] = As[cbuf][m0][ks + tig + 4];
                a[mt][3] = As[cbuf][m0 + 8][ks + tig + 4];
            }
#pragma unroll
            for (int nt = 0; nt < 8; nt++) {
                int n0 = wn + nt * 8 + gg;
                b[nt][0] = Bs[cbuf][ks + tig][n0];
                b[nt][1] = Bs[cbuf][ks + tig + 4][n0];
            }
#pragma unroll
            for (int mt = 0; mt < 2; mt++)
#pragma unroll
                for (int nt = 0; nt < 8; nt++)
                    mma_tf32(c[mt][nt], a[mt], b[nt]);
        }
        if (kt < NT - 1) {
#pragma unroll
            for (int u = 0; u < 4; u++) {
                int i = tid + u * 256;
                int row = i >> 4, kk = i & 15;
                As[nbuf][row][kk] = f2tf(avs[u]);
            }
#pragma unroll
            for (int u = 0; u < 4; u++) {
                int ff = tid + u * 256, krow = ff >> 6, cc = ff & 63;
                unsigned* q = &Bs[nbuf][krow][cc * 4];
                q[0] = f2tf(bv[u].x); q[1] = f2tf(bv[u].y); q[2] = f2tf(bv[u].z); q[3] = f2tf(bv[u].w);
            }
        }
        __syncthreads();
    }

    // epilogue: msg_input fp16 only (msg_0 is reconstructed on the fly)
#pragma unroll
    for (int mt = 0; mt < 2; mt++) {
#pragma unroll
        for (int nt = 0; nt < 8; nt++) {
            int col = wn + nt * 8 + tig * 2;
            long r0 = row0 + wm + mt * 16 + gg;
            if (r0 < E)
                g_msg_input[(r0 * 256 + col) >> 1] = f2h(make_float2(c[mt][nt][0], c[mt][nt][1]));
            long r1 = r0 + 8;
            if (r1 < E)
                g_msg_input[(r1 * 256 + col) >> 1] = f2h(make_float2(c[mt][nt][2], c[mt][nt][3]));
        }
    }
}

__global__ __launch_bounds__(256)
void k_out_tf32(const float* __restrict__ x_nodes, const float* __restrict__ W_o,
                const float* __restrict__ b_o, int N) {
    __shared__ unsigned As[2][64][APAD];
    __shared__ unsigned Bs[2][16][BPAD];
    int tid = threadIdx.x;
    int lane = tid & 31, wid = tid >> 5;
    int gg = lane >> 2, tig = lane & 3;
    int wm = (wid & 1) * 32, wn = (wid >> 1) * 64;
    long row0 = (long)blockIdx.x * 64;

    float c[2][8][4];
#pragma unroll
    for (int mt = 0; mt < 2; mt++)
#pragma unroll
        for (int nt = 0; nt < 8; nt++)
#pragma unroll
            for (int r = 0; r < 4; r++) c[mt][nt][r] = 0.f;

    const int NT = 19;
    {
#pragma unroll
        for (int u = 0; u < 4; u++) {
            int i = tid + u * 256;
            int row = i >> 4, kk = i & 15;
            long r = row0 + row;
            float v = 0.f;
            if (r < N && kk < 291)
                v = (kk < 35) ? x_nodes[r * 35 + kk] : g_m[r * 256 + (kk - 35)];
            As[0][row][kk] = f2tf(v);
        }
#pragma unroll
        for (int u = 0; u < 4; u++) {
            int ff = tid + u * 256, krow = ff >> 6, cc = ff & 63;
            float4 bvv = make_float4(0, 0, 0, 0);
            if (krow < 291) bvv = *(const float4*)&W_o[krow * 256 + cc * 4];
            unsigned* q = &Bs[0][krow][cc * 4];
            q[0] = f2tf(bvv.x); q[1] = f2tf(bvv.y); q[2] = f2tf(bvv.z); q[3] = f2tf(bvv.w);
        }
    }
    __syncthreads();

    for (int kt = 0; kt < NT; kt++) {
        int cbuf = kt & 1, nbuf = cbuf ^ 1;
        float avs[4]; float4 bv[4];
        if (kt < NT - 1) {
            int k0 = (kt + 1) * 16;
#pragma unroll
            for (int u = 0; u < 4; u++) {
                int i = tid + u * 256;
                int row = i >> 4, kk = i & 15;
                long r = row0 + row; int gk = k0 + kk;
                float v = 0.f;
                if (r < N && gk < 291)
                    v = (gk < 35) ? x_nodes[r * 35 + gk] : g_m[r * 256 + (gk - 35)];
                avs[u] = v;
            }
#pragma unroll
            for (int u = 0; u < 4; u++) {
                int ff = tid + u * 256, krow = ff >> 6, cc = ff & 63;
                int gk = k0 + krow;
                bv[u] = make_float4(0, 0, 0, 0);
                if (gk < 291) bv[u] = *(const float4*)&W_o[gk * 256 + cc * 4];
            }
        }
#pragma unroll
        for (int ks = 0; ks < 16; ks += 8) {
            unsigned a[2][4], b[8][2];
#pragma unroll
            for (int mt = 0; mt < 2; mt++) {
                int m0 = wm + mt * 16 + gg;
                a[mt][0] = As[cbuf][m0][ks + tig];
                a[mt][1] = As[cbuf][m0 + 8][ks + tig];
                a[mt][2] = As[cbuf][m0][ks + tig + 4];
                a[mt][3] = As[cbuf][m0 + 8][ks + tig + 4];
            }
#pragma unroll
            for (int nt = 0; nt < 8; nt++) {
                int n0 = wn + nt * 8 + gg;
                b[nt][0] = Bs[cbuf][ks + tig][n0];
                b[nt][1] = Bs[cbuf][ks + tig + 4][n0];
            }
#pragma unroll
            for (int mt = 0; mt < 2; mt++)
#pragma unroll
                for (int nt = 0; nt < 8; nt++)
                    mma_tf32(c[mt][nt], a[mt], b[nt]);
        }
        if (kt < NT - 1) {
#pragma unroll
            for (int u = 0; u < 4; u++) {
                int i = tid + u * 256;
                int row = i >> 4, kk = i & 15;
                As[nbuf][row][kk] = f2tf(avs[u]);
            }
#pragma unroll
            for (int u = 0; u < 4; u++) {
                int ff = tid + u * 256, krow = ff >> 6, cc = ff & 63;
                unsigned* q = &Bs[nbuf][krow][cc * 4];
                q[0] = f2tf(bv[u].x); q[1] = f2tf(bv[u].y); q[2] = f2tf(bv[u].z); q[3] = f2tf(bv[u].w);
            }
        }
        __syncthreads();
    }

#pragma unroll
    for (int mt = 0; mt < 2; mt++) {
#pragma unroll
        for (int nt = 0; nt < 8; nt++) {
            int col = wn + nt * 8 + tig * 2;
            float b0v = b_o[col], b1v = b_o[col + 1];
            long r0 = row0 + wm + mt * 16 + gg;
            if (r0 < N) {
                float2 o;
                o.x = fmaxf(c[mt][nt][0] + b0v, 0.f);
                o.y = fmaxf(c[mt][nt][1] + b1v, 0.f);
                *(float2*)&g_h[r0 * 256 + col] = o;
            }
            long r1 = r0 + 8;
            if (r1 < N) {
                float2 o;
                o.x = fmaxf(c[mt][nt][2] + b0v, 0.f);
                o.y = fmaxf(c[mt][nt][3] + b1v, 0.f);
                *(float2*)&g_h[r1 * 256 + col] = o;
            }
        }
    }
}

// per-graph mean over sorted graph_ids
__global__ void k_mean(const int* __restrict__ gid, float* __restrict__ out, int N) {
    int g = blockIdx.x;
    int t = threadIdx.x;
    int lo = 0, hi = N;
    while (lo < hi) { int m = (lo + hi) >> 1; if (gid[m] < g) lo = m + 1; else hi = m; }
    int s = lo;
    hi = N;
    while (lo < hi) { int m = (lo + hi) >> 1; if (gid[m] < g + 1) lo = m + 1; else hi = m; }
    int e = lo;
    float sum = 0.f;
    for (int n = s; n < e; n++) sum += g_h[n * HDIM + t];
    float c = (float)((e - s) > 0 ? (e - s) : 1);
    out[g * HDIM + t] = sum / c;
}

// ---------------- launcher ----------------
extern "C" void kernel_launch(void* const* d_in, const int* in_sizes, int n_in,
                              void* d_out, int out_size) {
    const float* x_nodes = (const float*)d_in[0];
    const float* x_edges = (const float*)d_in[1];
    const float* tree_m  = (const float*)d_in[2];
    const float* W_i     = (const float*)d_in[3];
    const float* W_h     = (const float*)d_in[4];
    const float* W_o     = (const float*)d_in[5];
    const float* b_o     = (const float*)d_in[6];
    const int*   esrc    = (const int*)d_in[7];
    const int*   edst    = (const int*)d_in[8];
    const int*   tgt     = (const int*)d_in[11];
    const int*   teid    = (const int*)d_in[12];
    const int*   gid     = (const int*)d_in[13];

    int N = in_sizes[0] / 35;
    int E = in_sizes[1] / 5;
    int K = in_sizes[11];
    int G = out_size / HDIM;
    float* out = (float*)d_out;

    int* d_node_ptr; cudaGetSymbolAddress((void**)&d_node_ptr, g_node_ptr);
    int* d_bt_ptr;   cudaGetSymbolAddress((void**)&d_bt_ptr, g_bt_ptr);

    cudaFuncSetAttribute(k_Z, cudaFuncAttributeMaxDynamicSharedMemorySize, Z_SMEM);

    // node in-edge CSR
    k_zero_cnt<<<(N + 255) / 256, 256>>>(N);
    k_count<<<(E + 255) / 256, 256>>>(edst, E);
    k_scan<<<1, 1024>>>(d_node_ptr, N, 1);
    k_place<<<(E + 255) / 256, 256>>>(edst, E);
    // backtrack CSR
    k_bt_count<<<(E + 255) / 256, 256>>>(esrc, edst, E);
    k_scan<<<1, 1024>>>(d_bt_ptr, E, 0);
    k_bt_fill<<<(E + 255) / 256, 256>>>(esrc, edst, E);

    k_convWt<<<(HDIM * HDIM / 2 + 255) / 256, 256>>>(W_h);
    k_zero_alpha<<<(N * HDIM + 255) / 256, 256>>>(N * HDIM);
    k_edge_tf32<<<(E + 63) / 64, 256>>>(x_nodes, x_edges, W_i, esrc, E);
    k_scatter_alpha<<<(K * 256 + 255) / 256, 256>>>(tree_m, tgt, teid, K);

    // BP iterations: ns_t -> corr_t -> Z_t (Z overwritten after corr uses Z_{t-1})
    for (int t = 0; t < 3; t++) {
        int first = (t == 0);
        int prevb = (t + 1) & 1;     // corr_{t-1} buffer ((t-1)&1)
        int curb  = t & 1;
        k_nodesum_f<<<(N + 3) / 4, 256>>>(esrc, first, 0, N, prevb);
        k_btcorr<<<BTCAP, 256>>>(esrc, E, first, prevb, curb);
        k_Z<<<(N + 63) / 64, 256, Z_SMEM>>>(N);
    }
    // final m = alpha + sum msg_3 (uses Z_2, corr_2 in buffer 0)
    k_nodesum_f<<<(N + 3) / 4, 256>>>(esrc, 0, 1, N, 0);

    k_out_tf32<<<(N + 63) / 64, 256>>>(x_nodes, W_o, b_o, N);
    k_mean<<<G, 256>>>(gid, out, N);
}